// round 13
// baseline (speedup 1.0000x reference)
#include <cuda_runtime.h>
#include <cuda_fp16.h>
#include <cstdint>

// Problem dims
#define MDIM 8192
#define NDIM 4096
#define KDIM 4096

// GEMM tiling — fp16 mma.sync path (tcgen05 unavailable: harness compiles via
// generic compute_103 which gates off the 'a'-suffix accelerated features).
// 256x128 CTA tile, 512 threads (16 warps, 4Mx4N grid, 64x32 warp tiles),
// BK=64, 3 stages. LDS traffic: 117 B/tensor-cycle (vs 127 at R11's 128x128),
// pulling the smem-crossbar floor below the tensor floor. 16 warps = 4/SMSP
// covers the per-chunk barrier at 1 CTA/SM.
#define BM 256
#define BN 128
#define BK 64
#define KCH (KDIM / BK)                 // 64
#define STAGES 3
#define ASTAGE (BM * 128)               // 32 KB
#define BSTAGE (BN * 128)               // 16 KB
#define STG_BYTES (ASTAGE + BSTAGE)     // 48 KB
#define SMEM_BYTES (STAGES * STG_BYTES) // 144 KB -> 1 CTA/SM
#define NTHREADS 512

// Scratch: fp16 preprocessed weight + fp16-rounded X.
__device__ __half g_wh[(size_t)NDIM * (size_t)KDIM];   // 32 MB
__device__ __half g_xh[(size_t)MDIM * (size_t)KDIM];   // 64 MB

// ---------------------------------------------------------------- helpers
__device__ __forceinline__ uint32_t smem_u32(const void* p) {
    uint32_t a;
    asm("{ .reg .u64 t; cvta.to.shared.u64 t, %1; cvt.u32.u64 %0, t; }"
        : "=r"(a) : "l"(p));
    return a;
}

__device__ __forceinline__ void cp16(uint32_t dst, const void* src) {
    asm volatile("cp.async.cg.shared.global [%0], [%1], 16;" :: "r"(dst), "l"(src));
}

__device__ __forceinline__ void ldsm4(uint32_t* r, uint32_t addr) {
    asm volatile("ldmatrix.sync.aligned.m8n8.x4.shared.b16 {%0,%1,%2,%3}, [%4];"
                 : "=r"(r[0]), "=r"(r[1]), "=r"(r[2]), "=r"(r[3]) : "r"(addr));
}

__device__ __forceinline__ void mma_f16(float* d, const uint32_t* a, const uint32_t* b) {
    asm volatile(
        "mma.sync.aligned.m16n8k16.row.col.f32.f16.f16.f32 "
        "{%0,%1,%2,%3}, {%4,%5,%6,%7}, {%8,%9}, {%0,%1,%2,%3};"
        : "+f"(d[0]), "+f"(d[1]), "+f"(d[2]), "+f"(d[3])
        : "r"(a[0]), "r"(a[1]), "r"(a[2]), "r"(a[3]), "r"(b[0]), "r"(b[1]));
}

// --------------------------------------------- fused preprocess kernel
// Blocks [0, NDIM): one block per weight row — mean-center, sign*mean|.|,
//   restore per-8-window argmax-|w| element, round to fp16 (RN) -> g_wh.
// Blocks [NDIM, ...): X fp32 -> fp16 (RN) -> g_xh.
__global__ __launch_bounds__(256, 1) void prep_all_kernel(const float* __restrict__ W,
                                                          const float* __restrict__ X) {
    __shared__ float srow[KDIM];
    __shared__ float sred[8];
    const int tid = threadIdx.x;

    if (blockIdx.x >= NDIM) {
        const size_t i = (size_t)(blockIdx.x - NDIM) * 256 + tid;   // 8-elt group
        float4 v0 = reinterpret_cast<const float4*>(X)[i * 2 + 0];
        float4 v1 = reinterpret_cast<const float4*>(X)[i * 2 + 1];
        __half o8[8];
        o8[0] = __float2half_rn(v0.x); o8[1] = __float2half_rn(v0.y);
        o8[2] = __float2half_rn(v0.z); o8[3] = __float2half_rn(v0.w);
        o8[4] = __float2half_rn(v1.x); o8[5] = __float2half_rn(v1.y);
        o8[6] = __float2half_rn(v1.z); o8[7] = __float2half_rn(v1.w);
        reinterpret_cast<uint4*>(g_xh)[i] = *reinterpret_cast<const uint4*>(o8);
        return;
    }

    const int row = blockIdx.x;
    const float* wr = W + (size_t)row * KDIM;

    float4* s4 = reinterpret_cast<float4*>(srow);
    const float4* g4 = reinterpret_cast<const float4*>(wr);
    for (int i = tid; i < KDIM / 4; i += 256) s4[i] = g4[i];
    __syncthreads();

    float a = 0.f;
    for (int i = tid; i < KDIM; i += 256) a += srow[i];
    #pragma unroll
    for (int o = 16; o; o >>= 1) a += __shfl_xor_sync(0xffffffffu, a, o);
    if ((tid & 31) == 0) sred[tid >> 5] = a;
    __syncthreads();
    if (tid == 0) {
        float t = 0.f;
        for (int j = 0; j < 8; j++) t += sred[j];
        sred[0] = t * (1.0f / KDIM);
    }
    __syncthreads();
    const float mu = sred[0];
    __syncthreads();

    float b = 0.f;
    for (int i = tid; i < KDIM; i += 256) b += fabsf(srow[i] - mu);
    #pragma unroll
    for (int o = 16; o; o >>= 1) b += __shfl_xor_sync(0xffffffffu, b, o);
    if ((tid & 31) == 0) sred[tid >> 5] = b;
    __syncthreads();
    if (tid == 0) {
        float t = 0.f;
        for (int j = 0; j < 8; j++) t += sred[j];
        sred[0] = t * (1.0f / KDIM);
    }
    __syncthreads();
    const float scale = sred[0];

    __half* outr = g_wh + (size_t)row * KDIM;
    for (int wdx = tid; wdx < KDIM / 8; wdx += 256) {
        const int base = wdx * 8;
        float v[8];
        #pragma unroll
        for (int j = 0; j < 8; j++) v[j] = srow[base + j];
        int best = 0;
        float bv = fabsf(v[0]);
        #pragma unroll
        for (int j = 1; j < 8; j++) {
            float av = fabsf(v[j]);
            if (av > bv) { bv = av; best = j; }   // strict > == first argmax
        }
        __half o8[8];
        #pragma unroll
        for (int j = 0; j < 8; j++) {
            float wc = v[j] - mu;
            float q = (wc > 0.f) ? scale : ((wc < 0.f) ? -scale : 0.f);
            if (j == best) q = v[j];
            o8[j] = __float2half_rn(q);
        }
        *reinterpret_cast<uint4*>(outr + base) = *reinterpret_cast<const uint4*>(o8);
    }
}

// ---------------------------------------------------------- fp16 GEMM kernel
// out[m,n] = sum_k g_xh[m,k] * g_wh[n,k] + bias[n]
// 256x128 CTA tile, 512 threads, BK=64, 3-stage cp.async, mma.sync.m16n8k16.
// Loop body is R11's proven form: batched ldsm per ks with fresh per-iteration
// registers (ptxas renames + pipelines; manual rotation regressed in R12).
__global__ __launch_bounds__(NTHREADS, 1) void gemm_kernel(const float* __restrict__ bias,
                                                           float* __restrict__ out) {
    extern __shared__ __align__(1024) char smem[];
    const uint32_t sbase = smem_u32(smem);
    const int tid = threadIdx.x;
    const int lane = tid & 31;
    const int wid = tid >> 5;
    const int wm = wid & 3;          // 4 warps along M (64 rows each)
    const int wn = wid >> 2;         // 4 warps along N (32 cols each)

    const int m0 = blockIdx.y * BM;
    const int n0 = blockIdx.x * BN;
    const __half* Xb = g_xh + (size_t)m0 * KDIM;
    const __half* Wb = g_wh + (size_t)n0 * KDIM;

    // ---- cp.async per-thread constants (16B = 8 halves per chunk) ----
    const int kb    = tid & 7;            // 16B chunk within 128B row
    const int rbase = tid >> 3;           // base row 0..63 (+= 64 per iteration)
    const uint32_t dA0 = (uint32_t)rbase * 128 + (uint32_t)((kb ^ (rbase & 7)) << 4);
    const uint32_t dB0 = ASTAGE + dA0;
    const __half* srcA0 = Xb + (size_t)rbase * KDIM + kb * 8;
    const __half* srcB0 = Wb + (size_t)rbase * KDIM + kb * 8;

    // ---- ldmatrix per-lane constants ----
    const int e7 = lane & 7;
    const int tA = lane >> 4;             // A: k-chunk select bit
    const int tB = (lane >> 3) & 1;       // B: k-chunk select bit
    uint32_t aoff[4], boff[2];
    #pragma unroll
    for (int mt = 0; mt < 4; mt++) {
        // A 16x16 tile: lanes 0-15 -> rows 0-15 (k 0-7), lanes 16-31 -> k 8-15
        const int rowAf = wm * 64 + mt * 16 + (lane & 15);
        aoff[mt] = (uint32_t)rowAf * 128;
    }
    #pragma unroll
    for (int ntp = 0; ntp < 2; ntp++) {
        // B 16(n)x16(k) tile: lanes {0-7,8-15} -> n 0-7 (k 0-7, 8-15),
        //                     lanes {16-23,24-31} -> n 8-15
        const int rowBf = wn * 32 + ntp * 16 + e7 + ((lane >> 4) & 1) * 8;
        boff[ntp] = ASTAGE + (uint32_t)rowBf * 128;
    }

    float acc[4][4][4];
    #pragma unroll
    for (int mt = 0; mt < 4; mt++)
        #pragma unroll
        for (int nt = 0; nt < 4; nt++)
            #pragma unroll
            for (int q = 0; q < 4; q++) acc[mt][nt][q] = 0.f;

    // ---- prologue: fill STAGES-1 stages ----
    #pragma unroll
    for (int s = 0; s < STAGES - 1; s++) {
        const uint32_t stg = sbase + s * STG_BYTES;
        #pragma unroll
        for (int i = 0; i < 4; i++)   // A: 256 rows, 64 rows/thread-step
            cp16(stg + dA0 + i * 8192, srcA0 + (size_t)i * 64 * KDIM + s * BK);
        #pragma unroll
        for (int i = 0; i < 2; i++)   // B: 128 rows
            cp16(stg + dB0 + i * 8192, srcB0 + (size_t)i * 64 * KDIM + s * BK);
        asm volatile("cp.async.commit_group;" ::: "memory");
    }

    // ---- main loop (one barrier per chunk; ring of 3 stages) ----
    int sc = 0;               // compute stage
    int sl = STAGES - 1;      // load stage for chunk c+STAGES-1
    for (int c = 0; c < KCH; c++) {
        asm volatile("cp.async.wait_group %0;" :: "n"(STAGES - 2) : "memory");
        __syncthreads();

        const int cn = c + STAGES - 1;
        if (cn < KCH) {
            const uint32_t stg = sbase + sl * STG_BYTES;
            #pragma unroll
            for (int i = 0; i < 4; i++)
                cp16(stg + dA0 + i * 8192, srcA0 + (size_t)i * 64 * KDIM + cn * BK);
            #pragma unroll
            for (int i = 0; i < 2; i++)
                cp16(stg + dB0 + i * 8192, srcB0 + (size_t)i * 64 * KDIM + cn * BK);
        }
        asm volatile("cp.async.commit_group;" ::: "memory");

        // compute chunk c: 4 k16 steps (fresh regs each ks — ptxas pipelines)
        const uint32_t stg = sbase + sc * STG_BYTES;
        #pragma unroll
        for (int ks = 0; ks < 4; ks++) {
            uint32_t af[4][4], bf[2][4];
            const uint32_t cA = (uint32_t)((((ks << 1) + tA) ^ e7) << 4);
            const uint32_t cB = (uint32_t)((((ks << 1) + tB) ^ e7) << 4);
            #pragma unroll
            for (int mt = 0; mt < 4; mt++) ldsm4(af[mt], stg + aoff[mt] + cA);
            #pragma unroll
            for (int ntp = 0; ntp < 2; ntp++) ldsm4(bf[ntp], stg + boff[ntp] + cB);
            #pragma unroll
            for (int mt = 0; mt < 4; mt++)
                #pragma unroll
                for (int ntp = 0; ntp < 2; ntp++) {
                    mma_f16(acc[mt][ntp * 2 + 0], af[mt], &bf[ntp][0]);
                    mma_f16(acc[mt][ntp * 2 + 1], af[mt], &bf[ntp][2]);
                }
        }
        sc = (sc + 1 == STAGES) ? 0 : sc + 1;
        sl = (sl + 1 == STAGES) ? 0 : sl + 1;
    }

    // ---- epilogue: bias add + store ----
    const int g = lane >> 2;
    const int tg = lane & 3;
    float2 bv[4];
    #pragma unroll
    for (int nt = 0; nt < 4; nt++)
        bv[nt] = *reinterpret_cast<const float2*>(bias + n0 + wn * 32 + nt * 8 + tg * 2);

    #pragma unroll
    for (int mt = 0; mt < 4; mt++) {
        const int row = m0 + wm * 64 + mt * 16 + g;
        float* o0 = out + (size_t)row * NDIM + n0 + wn * 32;
        float* o1 = o0 + 8 * NDIM;   // row + 8
        #pragma unroll
        for (int nt = 0; nt < 4; nt++) {
            const int col = nt * 8 + tg * 2;
            float2 v0, v1;
            v0.x = acc[mt][nt][0] + bv[nt].x;
            v0.y = acc[mt][nt][1] + bv[nt].y;
            v1.x = acc[mt][nt][2] + bv[nt].x;
            v1.y = acc[mt][nt][3] + bv[nt].y;
            *reinterpret_cast<float2*>(o0 + col) = v0;
            *reinterpret_cast<float2*>(o1 + col) = v1;
        }
    }
}

// ------------------------------------------------------------------ launch
extern "C" void kernel_launch(void* const* d_in, const int* in_sizes, int n_in,
                              void* d_out, int out_size) {
    (void)in_sizes; (void)n_in; (void)out_size;
    const float* X = (const float*)d_in[0];     // [4,2048,4096] -> [8192,4096]
    const float* W = (const float*)d_in[1];     // [4096,4096]
    const float* B = (const float*)d_in[2];     // [4096]
    float* O = (float*)d_out;                   // [8192,4096]

    const int conv_blocks = (MDIM * KDIM / 8) / 256;          // 16384
    prep_all_kernel<<<NDIM + conv_blocks, 256>>>(W, X);       // fused pre-pass

    cudaFuncSetAttribute(gemm_kernel, cudaFuncAttributeMaxDynamicSharedMemorySize, SMEM_BYTES);
    dim3 grid(NDIM / BN, MDIM / BM);            // (32, 32)
    gemm_kernel<<<grid, NTHREADS, SMEM_BYTES>>>(B, O);
}

// round 14
// speedup vs baseline: 1.1112x; 1.1112x over previous
#include <cuda_runtime.h>
#include <cuda_fp16.h>
#include <cstdint>

// Problem dims
#define MDIM 8192
#define NDIM 4096
#define KDIM 4096

// GEMM tiling — fp16 mma.sync path (tcgen05 unavailable: harness compiles via
// generic compute_103 which gates off the 'a'-suffix accelerated features).
// 128x128 CTA tile, BK=64, 3 stages, 2 CTAs/SM — R11 config, the empirical
// optimum: tensor floor == LDS-crossbar floor at this tiling, and both the
// 512-thread CTA (R13) and manual frag rotation (R12) regressed against it.
#define BM 128
#define BN 128
#define BK 64
#define KCH (KDIM / BK)                 // 64
#define STAGES 3
#define ASTAGE (BM * 128)               // 16 KB
#define BSTAGE (BN * 128)               // 16 KB
#define STG_BYTES (ASTAGE + BSTAGE)     // 32 KB
#define SMEM_BYTES (STAGES * STG_BYTES) // 96 KB -> 2 CTAs/SM

// Scratch: fp16 preprocessed weight + fp16-rounded X.
__device__ __half g_wh[(size_t)NDIM * (size_t)KDIM];   // 32 MB
__device__ __half g_xh[(size_t)MDIM * (size_t)KDIM];   // 64 MB

// ---------------------------------------------------------------- helpers
__device__ __forceinline__ uint32_t smem_u32(const void* p) {
    uint32_t a;
    asm("{ .reg .u64 t; cvta.to.shared.u64 t, %1; cvt.u32.u64 %0, t; }"
        : "=r"(a) : "l"(p));
    return a;
}

__device__ __forceinline__ void cp16(uint32_t dst, const void* src) {
    asm volatile("cp.async.cg.shared.global [%0], [%1], 16;" :: "r"(dst), "l"(src));
}

__device__ __forceinline__ void ldsm4(uint32_t* r, uint32_t addr) {
    asm volatile("ldmatrix.sync.aligned.m8n8.x4.shared.b16 {%0,%1,%2,%3}, [%4];"
                 : "=r"(r[0]), "=r"(r[1]), "=r"(r[2]), "=r"(r[3]) : "r"(addr));
}

__device__ __forceinline__ void mma_f16(float* d, const uint32_t* a, const uint32_t* b) {
    asm volatile(
        "mma.sync.aligned.m16n8k16.row.col.f32.f16.f16.f32 "
        "{%0,%1,%2,%3}, {%4,%5,%6,%7}, {%8,%9}, {%0,%1,%2,%3};"
        : "+f"(d[0]), "+f"(d[1]), "+f"(d[2]), "+f"(d[3])
        : "r"(a[0]), "r"(a[1]), "r"(a[2]), "r"(a[3]), "r"(b[0]), "r"(b[1]));
}

// --------------------------------------------- fused preprocess kernel
// Blocks [0, NDIM): one block per weight row, fully register-resident:
//   each thread owns 16 contiguous weights = exactly 2 outlier windows.
//   mean-center, sign*mean|.|, restore per-8-window argmax-|w| element,
//   round fp16 (RN) -> g_wh. No smem data staging (saves 3 row re-reads
//   through the crossbar and 2 barriers vs the staged version).
// Blocks [NDIM, ...): X fp32 -> fp16 (RN) -> g_xh (pure DRAM streaming).
__global__ __launch_bounds__(256, 1) void prep_all_kernel(const float* __restrict__ W,
                                                          const float* __restrict__ X) {
    __shared__ float sred[8];
    const int tid = threadIdx.x;

    if (blockIdx.x >= NDIM) {
        const size_t i = (size_t)(blockIdx.x - NDIM) * 256 + tid;   // 8-elt group
        float4 v0 = reinterpret_cast<const float4*>(X)[i * 2 + 0];
        float4 v1 = reinterpret_cast<const float4*>(X)[i * 2 + 1];
        __half o8[8];
        o8[0] = __float2half_rn(v0.x); o8[1] = __float2half_rn(v0.y);
        o8[2] = __float2half_rn(v0.z); o8[3] = __float2half_rn(v0.w);
        o8[4] = __float2half_rn(v1.x); o8[5] = __float2half_rn(v1.y);
        o8[6] = __float2half_rn(v1.z); o8[7] = __float2half_rn(v1.w);
        reinterpret_cast<uint4*>(g_xh)[i] = *reinterpret_cast<const uint4*>(o8);
        return;
    }

    const int row = blockIdx.x;
    const float* wr = W + (size_t)row * KDIM + tid * 16;

    // 16 weights per thread (2 windows of 8), register-resident.
    float v[16];
    #pragma unroll
    for (int q = 0; q < 4; q++) {
        float4 t = *reinterpret_cast<const float4*>(wr + q * 4);
        v[q * 4 + 0] = t.x; v[q * 4 + 1] = t.y;
        v[q * 4 + 2] = t.z; v[q * 4 + 3] = t.w;
    }

    // block reduction: sum
    float a = 0.f;
    #pragma unroll
    for (int j = 0; j < 16; j++) a += v[j];
    #pragma unroll
    for (int o = 16; o; o >>= 1) a += __shfl_xor_sync(0xffffffffu, a, o);
    if ((tid & 31) == 0) sred[tid >> 5] = a;
    __syncthreads();
    if (tid == 0) {
        float t = 0.f;
        for (int j = 0; j < 8; j++) t += sred[j];
        sred[0] = t * (1.0f / KDIM);
    }
    __syncthreads();
    const float mu = sred[0];
    __syncthreads();

    // block reduction: mean |w - mu|
    float b = 0.f;
    #pragma unroll
    for (int j = 0; j < 16; j++) b += fabsf(v[j] - mu);
    #pragma unroll
    for (int o = 16; o; o >>= 1) b += __shfl_xor_sync(0xffffffffu, b, o);
    if ((tid & 31) == 0) sred[tid >> 5] = b;
    __syncthreads();
    if (tid == 0) {
        float t = 0.f;
        for (int j = 0; j < 8; j++) t += sred[j];
        sred[0] = t * (1.0f / KDIM);
    }
    __syncthreads();
    const float scale = sred[0];

    // binarize + restore per-window outlier, 2 windows from registers
    __half o16[16];
    #pragma unroll
    for (int w8 = 0; w8 < 2; w8++) {
        const float* vw = v + w8 * 8;
        int best = 0;
        float bv = fabsf(vw[0]);
        #pragma unroll
        for (int j = 1; j < 8; j++) {
            float av = fabsf(vw[j]);
            if (av > bv) { bv = av; best = j; }   // strict > == first argmax
        }
        #pragma unroll
        for (int j = 0; j < 8; j++) {
            float wc = vw[j] - mu;
            float q = (wc > 0.f) ? scale : ((wc < 0.f) ? -scale : 0.f);
            if (j == best) q = vw[j];
            o16[w8 * 8 + j] = __float2half_rn(q);
        }
    }
    __half* outr = g_wh + (size_t)row * KDIM + tid * 16;
    *reinterpret_cast<uint4*>(outr)     = *reinterpret_cast<const uint4*>(o16);
    *reinterpret_cast<uint4*>(outr + 8) = *reinterpret_cast<const uint4*>(o16 + 8);
}

// ---------------------------------------------------------- fp16 GEMM kernel
// out[m,n] = sum_k g_xh[m,k] * g_wh[n,k] + bias[n]
// 128x128 CTA tile, BK=64, 3-stage cp.async, 2 CTAs/SM, mma.sync.m16n8k16.
// Exact R11 loop body (batched ldsm per ks, fresh per-iteration registers).
__global__ __launch_bounds__(256, 2) void gemm_kernel(const float* __restrict__ bias,
                                                      float* __restrict__ out) {
    extern __shared__ __align__(1024) char smem[];
    const uint32_t sbase = smem_u32(smem);
    const int tid = threadIdx.x;
    const int lane = tid & 31;
    const int wid = tid >> 5;
    const int wm = wid & 1;          // 2 warps along M (64 rows each)
    const int wn = wid >> 1;         // 4 warps along N (32 cols each)

    const int m0 = blockIdx.y * BM;
    const int n0 = blockIdx.x * BN;
    const __half* Xb = g_xh + (size_t)m0 * KDIM;
    const __half* Wb = g_wh + (size_t)n0 * KDIM;

    // ---- cp.async per-thread constants (16B = 8 halves per chunk) ----
    const int kb    = tid & 7;            // 16B chunk within 128B row
    const int rbase = tid >> 3;           // base row (+= 32 per iteration)
    const uint32_t dA0 = (uint32_t)rbase * 128 + (uint32_t)((kb ^ (rbase & 7)) << 4);
    const uint32_t dB0 = ASTAGE + dA0;
    const __half* srcA0 = Xb + (size_t)rbase * KDIM + kb * 8;
    const __half* srcB0 = Wb + (size_t)rbase * KDIM + kb * 8;

    // ---- ldmatrix per-lane constants ----
    const int e7 = lane & 7;
    const int tA = lane >> 4;             // A: k-chunk select bit
    const int tB = (lane >> 3) & 1;       // B: k-chunk select bit
    uint32_t aoff[4], boff[2];
    #pragma unroll
    for (int mt = 0; mt < 4; mt++) {
        // A 16x16 tile: lanes 0-15 -> rows 0-15 (k 0-7), lanes 16-31 -> k 8-15
        const int rowAf = wm * 64 + mt * 16 + (lane & 15);
        aoff[mt] = (uint32_t)rowAf * 128;
    }
    #pragma unroll
    for (int ntp = 0; ntp < 2; ntp++) {
        // B 16(n)x16(k) tile: lanes {0-7,8-15} -> n 0-7 (k 0-7, 8-15),
        //                     lanes {16-23,24-31} -> n 8-15
        const int rowBf = wn * 32 + ntp * 16 + e7 + ((lane >> 4) & 1) * 8;
        boff[ntp] = ASTAGE + (uint32_t)rowBf * 128;
    }

    float acc[4][4][4];
    #pragma unroll
    for (int mt = 0; mt < 4; mt++)
        #pragma unroll
        for (int nt = 0; nt < 4; nt++)
            #pragma unroll
            for (int q = 0; q < 4; q++) acc[mt][nt][q] = 0.f;

    // ---- prologue: fill STAGES-1 stages ----
    #pragma unroll
    for (int s = 0; s < STAGES - 1; s++) {
        const uint32_t stg = sbase + s * STG_BYTES;
        #pragma unroll
        for (int i = 0; i < 4; i++)
            cp16(stg + dA0 + i * 4096, srcA0 + (size_t)i * 32 * KDIM + s * BK);
        #pragma unroll
        for (int i = 0; i < 4; i++)
            cp16(stg + dB0 + i * 4096, srcB0 + (size_t)i * 32 * KDIM + s * BK);
        asm volatile("cp.async.commit_group;" ::: "memory");
    }

    // ---- main loop (one barrier per chunk; ring of 3 stages) ----
    int sc = 0;               // compute stage
    int sl = STAGES - 1;      // load stage for chunk c+STAGES-1
    for (int c = 0; c < KCH; c++) {
        asm volatile("cp.async.wait_group %0;" :: "n"(STAGES - 2) : "memory");
        __syncthreads();

        const int cn = c + STAGES - 1;
        if (cn < KCH) {
            const uint32_t stg = sbase + sl * STG_BYTES;
            #pragma unroll
            for (int i = 0; i < 4; i++)
                cp16(stg + dA0 + i * 4096, srcA0 + (size_t)i * 32 * KDIM + cn * BK);
            #pragma unroll
            for (int i = 0; i < 4; i++)
                cp16(stg + dB0 + i * 4096, srcB0 + (size_t)i * 32 * KDIM + cn * BK);
        }
        asm volatile("cp.async.commit_group;" ::: "memory");

        // compute chunk c: 4 k16 steps (fresh regs each ks — ptxas pipelines)
        const uint32_t stg = sbase + sc * STG_BYTES;
        #pragma unroll
        for (int ks = 0; ks < 4; ks++) {
            uint32_t af[4][4], bf[2][4];
            const uint32_t cA = (uint32_t)((((ks << 1) + tA) ^ e7) << 4);
            const uint32_t cB = (uint32_t)((((ks << 1) + tB) ^ e7) << 4);
            #pragma unroll
            for (int mt = 0; mt < 4; mt++) ldsm4(af[mt], stg + aoff[mt] + cA);
            #pragma unroll
            for (int ntp = 0; ntp < 2; ntp++) ldsm4(bf[ntp], stg + boff[ntp] + cB);
            #pragma unroll
            for (int mt = 0; mt < 4; mt++)
                #pragma unroll
                for (int ntp = 0; ntp < 2; ntp++) {
                    mma_f16(acc[mt][ntp * 2 + 0], af[mt], &bf[ntp][0]);
                    mma_f16(acc[mt][ntp * 2 + 1], af[mt], &bf[ntp][2]);
                }
        }
        sc = (sc + 1 == STAGES) ? 0 : sc + 1;
        sl = (sl + 1 == STAGES) ? 0 : sl + 1;
    }

    // ---- epilogue: bias add + store ----
    const int g = lane >> 2;
    const int tg = lane & 3;
    float2 bv[4];
    #pragma unroll
    for (int nt = 0; nt < 4; nt++)
        bv[nt] = *reinterpret_cast<const float2*>(bias + n0 + wn * 32 + nt * 8 + tg * 2);

    #pragma unroll
    for (int mt = 0; mt < 4; mt++) {
        const int row = m0 + wm * 64 + mt * 16 + g;
        float* o0 = out + (size_t)row * NDIM + n0 + wn * 32;
        float* o1 = o0 + 8 * NDIM;   // row + 8
        #pragma unroll
        for (int nt = 0; nt < 4; nt++) {
            const int col = nt * 8 + tg * 2;
            float2 v0, v1;
            v0.x = acc[mt][nt][0] + bv[nt].x;
            v0.y = acc[mt][nt][1] + bv[nt].y;
            v1.x = acc[mt][nt][2] + bv[nt].x;
            v1.y = acc[mt][nt][3] + bv[nt].y;
            *reinterpret_cast<float2*>(o0 + col) = v0;
            *reinterpret_cast<float2*>(o1 + col) = v1;
        }
    }
}

// ------------------------------------------------------------------ launch
extern "C" void kernel_launch(void* const* d_in, const int* in_sizes, int n_in,
                              void* d_out, int out_size) {
    (void)in_sizes; (void)n_in; (void)out_size;
    const float* X = (const float*)d_in[0];     // [4,2048,4096] -> [8192,4096]
    const float* W = (const float*)d_in[1];     // [4096,4096]
    const float* B = (const float*)d_in[2];     // [4096]
    float* O = (float*)d_out;                   // [8192,4096]

    const int conv_blocks = (MDIM * KDIM / 8) / 256;          // 16384
    prep_all_kernel<<<NDIM + conv_blocks, 256>>>(W, X);       // fused pre-pass

    cudaFuncSetAttribute(gemm_kernel, cudaFuncAttributeMaxDynamicSharedMemorySize, SMEM_BYTES);
    dim3 grid(NDIM / BN, MDIM / BM);            // (32, 64)
    gemm_kernel<<<grid, 256, SMEM_BYTES>>>(B, O);
}